// round 9
// baseline (speedup 1.0000x reference)
#include <cuda_runtime.h>

// Problem constants (fixed-shape problem; grids still derived from in_sizes).
#define MAX_NODES 50000
#define CAP       128           // bucket capacity per node; P(deg>=128) ~ e^-150

// ---------------- device scratch (no allocations allowed) ----------------
__device__ int   g_deg[MAX_NODES];
__device__ int   g_bucket[MAX_NODES * CAP];     // 25.6 MB
__device__ float g_mean[MAX_NODES * 64];        // 12.8 MB
__device__ float g_Bt[128 * 128];               // combined [W_l;W_r] transposed: Bt[k][n]

// ---------------- packed f32x2 helpers (Blackwell) ----------------
#define FMA_F32X2(d, a, b) \
    asm("fma.rn.f32x2 %0, %1, %2, %0;" : "+l"(d) : "l"(a), "l"(b))
#define PACK_DUP_F32X2(out, s) \
    asm("mov.b64 %0, {%1, %1};" : "=l"(out) : "f"(s))
#define PACK_F32X2(out, lo, hi) \
    asm("mov.b64 %0, {%1, %2};" : "=l"(out) : "f"(lo), "f"(hi))
#define UNPACK_F32X2(lo, hi, in) \
    asm("mov.b64 {%0, %1}, %2;" : "=f"(lo), "=f"(hi) : "l"(in))

// ---------------- kernel 1: zero degrees + transpose weights (merged) ----------------
// Bt[k][n] = (k<64) ? W_l[n][k] : W_r[n][k-64]
__global__ void k_init(const float* __restrict__ W_l,
                       const float* __restrict__ W_r, int nN) {
    int i = blockIdx.x * blockDim.x + threadIdx.x;
    if (i < nN) g_deg[i] = 0;
    if (i < 128 * 128) {
        int k = i & 127;
        int n = i >> 7;
        float v = (k < 64) ? W_l[n * 64 + k] : W_r[n * 64 + (k - 64)];
        g_Bt[k * 128 + n] = v;
    }
}

// ---------------- kernel 2: bucket fill (CSR-lite, no scan) ----------------
// edge_index is INT32 on device (JAX default x64-disabled downcasts int64).
__global__ void k_fill_buckets(const int* __restrict__ ei, int nE, int nN) {
    int e = blockIdx.x * blockDim.x + threadIdx.x;
    if (e >= nE) return;
    int s = ei[e];               // src row   (edge_index[0][e])
    int d = ei[nE + e];          // dst row   (edge_index[1][e])
    if ((unsigned)s >= (unsigned)nN || (unsigned)d >= (unsigned)nN) return;
    int slot = atomicAdd(&g_deg[d], 1);
    if (slot < CAP) g_bucket[d * CAP + slot] = s;
}

// ---------------- kernel 3: mean aggregation (R6 version — best measured) ----------
// One warp per node. Two neighbors per warp iteration:
// lanes 0-15 read float4 of neighbor (2p), lanes 16-31 of neighbor (2p+1).
__global__ void k_aggregate(const float* __restrict__ x, int nN) {
    int gwarp = (blockIdx.x * blockDim.x + threadIdx.x) >> 5;
    int lane  = threadIdx.x & 31;
    if (gwarp >= nN) return;
    int node = gwarp;
    int deg  = g_deg[node];
    int m    = min(deg, CAP);

    const float4* __restrict__ x4 = (const float4*)x;   // 64 f32 = 16 float4 per row
    const int* __restrict__ bkt = &g_bucket[node * CAP];

    int col  = lane & 15;
    int half = lane >> 4;

    float4 acc = make_float4(0.f, 0.f, 0.f, 0.f);
    for (int base = 0; base < m; base += 32) {
        int cnt = min(32, m - base);
        int sid = (lane < cnt) ? bkt[base + lane] : -1;
        int pairs = (cnt + 1) >> 1;
        #pragma unroll 4
        for (int p = 0; p < pairs; p++) {
            int s = __shfl_sync(0xffffffffu, sid, 2 * p + half);
            if (s >= 0) {
                float4 v = x4[(size_t)s * 16 + col];    // half-warp reads 256B row
                acc.x += v.x; acc.y += v.y;
                acc.z += v.z; acc.w += v.w;
            }
        }
    }
    // combine the two half-warp partial sums
    acc.x += __shfl_xor_sync(0xffffffffu, acc.x, 16);
    acc.y += __shfl_xor_sync(0xffffffffu, acc.y, 16);
    acc.z += __shfl_xor_sync(0xffffffffu, acc.z, 16);
    acc.w += __shfl_xor_sync(0xffffffffu, acc.w, 16);

    if (half == 0) {
        float inv = 1.0f / fmaxf((float)deg, 1.0f);
        acc.x *= inv; acc.y *= inv; acc.z *= inv; acc.w *= inv;
        ((float4*)g_mean)[(size_t)node * 16 + col] = acc;
    }
}

// ---------------- kernel 4: fused GEMM + bias (f32x2 FMA) ----------------
// out[m, n] = sum_k A[m,k] * Bt[k,n] + b_l[n],   A = [mean || x] (K=128)
// Tile: 64 nodes x 128 outs per block, 256 threads, thread tile 4m x 8n.
// A in smem padded to 132 floats/row (bank-conflict-free dual-ty broadcast);
// acc RAW chains broken: 16 independent FMA2 between reuses of any acc reg.
#define A_STRIDE4 33            // float4 row stride for padded A (132 floats)
__global__ void __launch_bounds__(256, 2)
k_gemm(const float* __restrict__ x,
       const float* __restrict__ b_l,
       float* __restrict__ out, int nN) {
    extern __shared__ float smem[];
    float* A_s = smem;                    // [64][132]  33.8 KB (padded)
    float* B_s = smem + 64 * 132;         // [128][128] 64 KB (k-major)

    int tid    = threadIdx.x;
    int blockM = blockIdx.x * 64;

    // --- stage A tile: A[m][0:64]=mean row, A[m][64:128]=x row ---
    const float4* __restrict__ mean4 = (const float4*)g_mean;
    const float4* __restrict__ x4    = (const float4*)x;
    float4* A4s = (float4*)A_s;
    #pragma unroll
    for (int i = tid; i < 64 * 32; i += 256) {
        int mrow = i >> 5;
        int q    = i & 31;
        int gm   = blockM + mrow;
        float4 v = make_float4(0.f, 0.f, 0.f, 0.f);
        if (gm < nN)
            v = (q < 16) ? mean4[(size_t)gm * 16 + q]
                         : x4[(size_t)gm * 16 + (q - 16)];
        A4s[mrow * A_STRIDE4 + q] = v;
    }

    // --- stage B tile (identical for all blocks; L2-resident after first wave) ---
    {
        float4* B4s = (float4*)B_s;
        const float4* __restrict__ Bt4 = (const float4*)g_Bt;
        #pragma unroll
        for (int i = tid; i < 128 * 32; i += 256) B4s[i] = Bt4[i];
    }
    __syncthreads();

    int tx = tid & 15;              // n0 = tx*8 (0..120)
    int ty = tid >> 4;              // m0 = ty*4 (0..60)
    int n0 = tx * 8;
    int m0 = ty * 4;

    const ulonglong2* __restrict__ B8 = (const ulonglong2*)B_s;  // 4 floats/elem

    // packed accumulators: acc[i][j] = (out[m0+i][n0+2j], out[m0+i][n0+2j+1])
    unsigned long long acc[4][4];
    {
        float4 bia0 = *(const float4*)&b_l[n0];
        float4 bia1 = *(const float4*)&b_l[n0 + 4];
        unsigned long long b0, b1, b2, b3;
        PACK_F32X2(b0, bia0.x, bia0.y);
        PACK_F32X2(b1, bia0.z, bia0.w);
        PACK_F32X2(b2, bia1.x, bia1.y);
        PACK_F32X2(b3, bia1.z, bia1.w);
        #pragma unroll
        for (int i = 0; i < 4; i++) {
            acc[i][0] = b0; acc[i][1] = b1; acc[i][2] = b2; acc[i][3] = b3;
        }
    }

    // Inner: per 4 k-steps: 4 A LDS.128 (broadcast) + 8 B LDS.128,
    // 16 dup-packs (alu), 64 FMA2 (fma). Within each k-step s, the 16 FMA2
    // (4 rows x 4 n-pairs) are mutually independent -> no acc RAW stalls.
    #pragma unroll 4
    for (int kq = 0; kq < 32; kq++) {
        float av[4][4];
        #pragma unroll
        for (int i = 0; i < 4; i++) {
            float4 a = A4s[(m0 + i) * A_STRIDE4 + kq];
            av[i][0] = a.x; av[i][1] = a.y; av[i][2] = a.z; av[i][3] = a.w;
        }
        #pragma unroll
        for (int s = 0; s < 4; s++) {
            int k = kq * 4 + s;
            ulonglong2 blo = B8[k * 32 + tx * 2];
            ulonglong2 bhi = B8[k * 32 + tx * 2 + 1];
            #pragma unroll
            for (int i = 0; i < 4; i++) {
                unsigned long long ap;
                PACK_DUP_F32X2(ap, av[i][s]);
                FMA_F32X2(acc[i][0], ap, blo.x);
                FMA_F32X2(acc[i][1], ap, blo.y);
                FMA_F32X2(acc[i][2], ap, bhi.x);
                FMA_F32X2(acc[i][3], ap, bhi.y);
            }
        }
    }

    #pragma unroll
    for (int i = 0; i < 4; i++) {
        int gm = blockM + m0 + i;
        if (gm < nN) {
            float4 r0, r1;
            UNPACK_F32X2(r0.x, r0.y, acc[i][0]);
            UNPACK_F32X2(r0.z, r0.w, acc[i][1]);
            UNPACK_F32X2(r1.x, r1.y, acc[i][2]);
            UNPACK_F32X2(r1.z, r1.w, acc[i][3]);
            float4* o = (float4*)&out[(size_t)gm * 128 + n0];
            o[0] = r0;
            o[1] = r1;
        }
    }
}

// ---------------- launch ----------------
extern "C" void kernel_launch(void* const* d_in, const int* in_sizes, int n_in,
                              void* d_out, int out_size) {
    const float* x   = (const float*)d_in[0];       // [N, 64]
    const int*   ei  = (const int*)d_in[1];         // [2, E] int32 (JAX x64 off)
    const float* W_l = (const float*)d_in[2];       // [128, 64]
    const float* b_l = (const float*)d_in[3];       // [128]
    const float* W_r = (const float*)d_in[4];       // [128, 64]
    float*       out = (float*)d_out;               // [N, 128]

    int nN = in_sizes[0] / 64;
    int nE = in_sizes[1] / 2;

    int initN = (nN > 128 * 128) ? nN : 128 * 128;
    k_init<<<(initN + 255) / 256, 256>>>(W_l, W_r, nN);
    k_fill_buckets<<<(nE + 255) / 256, 256>>>(ei, nE, nN);
    k_aggregate<<<(nN + 7) / 8, 256>>>(x, nN);

    int smem_bytes = (64 * 132 + 128 * 128) * sizeof(float);   // 99328
    cudaFuncSetAttribute(k_gemm, cudaFuncAttributeMaxDynamicSharedMemorySize,
                         smem_bytes);
    k_gemm<<<(nN + 63) / 64, 256, smem_bytes>>>(x, b_l, out, nN);
}

// round 10
// speedup vs baseline: 1.2375x; 1.2375x over previous
#include <cuda_runtime.h>

// Problem constants (fixed-shape problem; grids still derived from in_sizes).
#define MAX_NODES 50000
#define CAP       128           // bucket capacity per node; P(deg>=128) ~ e^-150

// ---------------- device scratch (no allocations allowed) ----------------
__device__ int   g_deg[MAX_NODES];
__device__ int   g_bucket[MAX_NODES * CAP];     // 25.6 MB
__device__ float g_mean[MAX_NODES * 64];        // 12.8 MB
__device__ float g_Bt[128 * 128];               // combined [W_l;W_r] transposed: Bt[k][n]

// ---------------- packed f32x2 helpers (Blackwell) ----------------
#define FMA_F32X2(d, a, b) \
    asm("fma.rn.f32x2 %0, %1, %2, %0;" : "+l"(d) : "l"(a), "l"(b))
#define PACK_DUP_F32X2(out, s) \
    asm("mov.b64 %0, {%1, %1};" : "=l"(out) : "f"(s))
#define PACK_F32X2(out, lo, hi) \
    asm("mov.b64 %0, {%1, %2};" : "=l"(out) : "f"(lo), "f"(hi))
#define UNPACK_F32X2(lo, hi, in) \
    asm("mov.b64 {%0, %1}, %2;" : "=f"(lo), "=f"(hi) : "l"(in))

// ---------------- kernel 1: zero degrees + transpose weights (merged) ----------------
// Bt[k][n] = (k<64) ? W_l[n][k] : W_r[n][k-64]
__global__ void k_init(const float* __restrict__ W_l,
                       const float* __restrict__ W_r, int nN) {
    int i = blockIdx.x * blockDim.x + threadIdx.x;
    if (i < nN) g_deg[i] = 0;
    if (i < 128 * 128) {
        int k = i & 127;
        int n = i >> 7;
        float v = (k < 64) ? W_l[n * 64 + k] : W_r[n * 64 + (k - 64)];
        g_Bt[k * 128 + n] = v;
    }
}

// ---------------- kernel 2: bucket fill (CSR-lite, no scan) ----------------
// edge_index is INT32 on device (JAX default x64-disabled downcasts int64).
__global__ void k_fill_buckets(const int* __restrict__ ei, int nE, int nN) {
    int e = blockIdx.x * blockDim.x + threadIdx.x;
    if (e >= nE) return;
    int s = ei[e];               // src row   (edge_index[0][e])
    int d = ei[nE + e];          // dst row   (edge_index[1][e])
    if ((unsigned)s >= (unsigned)nN || (unsigned)d >= (unsigned)nN) return;
    int slot = atomicAdd(&g_deg[d], 1);
    if (slot < CAP) g_bucket[d * CAP + slot] = s;
}

// ---------------- kernel 3: mean aggregation (R6 version — best measured) ----------
// One warp per node. Two neighbors per warp iteration:
// lanes 0-15 read float4 of neighbor (2p), lanes 16-31 of neighbor (2p+1).
__global__ void k_aggregate(const float* __restrict__ x, int nN) {
    int gwarp = (blockIdx.x * blockDim.x + threadIdx.x) >> 5;
    int lane  = threadIdx.x & 31;
    if (gwarp >= nN) return;
    int node = gwarp;
    int deg  = g_deg[node];
    int m    = min(deg, CAP);

    const float4* __restrict__ x4 = (const float4*)x;   // 64 f32 = 16 float4 per row
    const int* __restrict__ bkt = &g_bucket[node * CAP];

    int col  = lane & 15;
    int half = lane >> 4;

    float4 acc = make_float4(0.f, 0.f, 0.f, 0.f);
    for (int base = 0; base < m; base += 32) {
        int cnt = min(32, m - base);
        int sid = (lane < cnt) ? bkt[base + lane] : -1;
        int pairs = (cnt + 1) >> 1;
        #pragma unroll 4
        for (int p = 0; p < pairs; p++) {
            int s = __shfl_sync(0xffffffffu, sid, 2 * p + half);
            if (s >= 0) {
                float4 v = x4[(size_t)s * 16 + col];    // half-warp reads 256B row
                acc.x += v.x; acc.y += v.y;
                acc.z += v.z; acc.w += v.w;
            }
        }
    }
    // combine the two half-warp partial sums
    acc.x += __shfl_xor_sync(0xffffffffu, acc.x, 16);
    acc.y += __shfl_xor_sync(0xffffffffu, acc.y, 16);
    acc.z += __shfl_xor_sync(0xffffffffu, acc.z, 16);
    acc.w += __shfl_xor_sync(0xffffffffu, acc.w, 16);

    if (half == 0) {
        float inv = 1.0f / fmaxf((float)deg, 1.0f);
        acc.x *= inv; acc.y *= inv; acc.z *= inv; acc.w *= inv;
        ((float4*)g_mean)[(size_t)node * 16 + col] = acc;
    }
}

// ---------------- kernel 4: fused GEMM + bias (R6 shape, k-chunked B, 3 CTAs/SM) ----
// out[m, n] = sum_k A[m,k] * Bt[k,n] + b_l[n],   A = [mean || x] (K=128)
// Tile: 64 nodes x 128 outs per block, 256 threads, thread tile 8m x 4n
// (warp-uniform A reads). B is staged in TWO 64-k chunks of 32 KB so total
// smem = 64 KB -> 3 CTAs/SM (24 warps) instead of R6's 2 CTAs at 96 KB.
__global__ void __launch_bounds__(256, 3)
k_gemm(const float* __restrict__ x,
       const float* __restrict__ b_l,
       float* __restrict__ out, int nN) {
    extern __shared__ float smem[];
    float* A_s = smem;              // [64][128]  32 KB
    float* B_s = smem + 64 * 128;   // [64][128]  32 KB (current k-chunk, k-major)

    int tid    = threadIdx.x;
    int blockM = blockIdx.x * 64;

    // --- stage A tile: A[m][0:64]=mean row, A[m][64:128]=x row (float4 copies) ---
    const float4* __restrict__ mean4 = (const float4*)g_mean;
    const float4* __restrict__ x4    = (const float4*)x;
    float4* A4s = (float4*)A_s;
    #pragma unroll
    for (int i = tid; i < 64 * 32; i += 256) {
        int mrow = i >> 5;          // 0..63
        int q    = i & 31;          // float4 index within 128-float row
        int gm   = blockM + mrow;
        float4 v = make_float4(0.f, 0.f, 0.f, 0.f);
        if (gm < nN)
            v = (q < 16) ? mean4[(size_t)gm * 16 + q]
                         : x4[(size_t)gm * 16 + (q - 16)];
        A4s[i] = v;
    }

    int tx = tid & 31;              // output group: n0 = tx*4 (0..124)
    int ty = tid >> 5;              // node group:   m0 = ty*8 (warp-uniform)
    int n0 = tx * 4;
    int m0 = ty * 8;

    float4* B4s = (float4*)B_s;
    const float4* __restrict__ Bt4 = (const float4*)g_Bt;
    const ulonglong2* __restrict__ B8 = (const ulonglong2*)B_s;  // 4 floats / elem

    // packed accumulators: acc01[i] = (out[n0], out[n0+1]), acc23 = (n0+2, n0+3)
    unsigned long long acc01[8], acc23[8];
    {
        float4 bias = *(const float4*)&b_l[n0];
        unsigned long long b01, b23;
        PACK_F32X2(b01, bias.x, bias.y);
        PACK_F32X2(b23, bias.z, bias.w);
        #pragma unroll
        for (int i = 0; i < 8; i++) { acc01[i] = b01; acc23[i] = b23; }
    }

    // ---- two 64-k chunks; B restaged per chunk, acc persists ----
    #pragma unroll 1
    for (int kc = 0; kc < 2; kc++) {
        // stage B chunk: B_s[kk][n] = g_Bt[kc*64 + kk][n]
        const float4* src = Bt4 + kc * 64 * 32;
        #pragma unroll
        for (int i = tid; i < 64 * 32; i += 256) B4s[i] = src[i];
        __syncthreads();

        int kqBase = kc * 16;       // A float4 index base for this chunk
        // Inner: per 4 k-steps, 4 B LDS.128 + 8 broadcast A LDS.128,
        // 32 dup-packs (alu), 64 FMA2 (fma).
        #pragma unroll 2
        for (int k = 0; k < 64; k += 4) {
            ulonglong2 b0 = B8[(k + 0) * 32 + tx];
            ulonglong2 b1 = B8[(k + 1) * 32 + tx];
            ulonglong2 b2 = B8[(k + 2) * 32 + tx];
            ulonglong2 b3 = B8[(k + 3) * 32 + tx];
            #pragma unroll
            for (int i = 0; i < 8; i++) {
                float4 a = A4s[(m0 + i) * 32 + kqBase + (k >> 2)];  // warp-broadcast
                unsigned long long ap;
                PACK_DUP_F32X2(ap, a.x);
                FMA_F32X2(acc01[i], ap, b0.x);
                FMA_F32X2(acc23[i], ap, b0.y);
                PACK_DUP_F32X2(ap, a.y);
                FMA_F32X2(acc01[i], ap, b1.x);
                FMA_F32X2(acc23[i], ap, b1.y);
                PACK_DUP_F32X2(ap, a.z);
                FMA_F32X2(acc01[i], ap, b2.x);
                FMA_F32X2(acc23[i], ap, b2.y);
                PACK_DUP_F32X2(ap, a.w);
                FMA_F32X2(acc01[i], ap, b3.x);
                FMA_F32X2(acc23[i], ap, b3.y);
            }
        }
        __syncthreads();            // before restaging B (and harmless on last)
    }

    #pragma unroll
    for (int i = 0; i < 8; i++) {
        int gm = blockM + m0 + i;
        if (gm < nN) {
            float4 r;
            UNPACK_F32X2(r.x, r.y, acc01[i]);
            UNPACK_F32X2(r.z, r.w, acc23[i]);
            *(float4*)&out[(size_t)gm * 128 + n0] = r;
        }
    }
}

// ---------------- launch ----------------
extern "C" void kernel_launch(void* const* d_in, const int* in_sizes, int n_in,
                              void* d_out, int out_size) {
    const float* x   = (const float*)d_in[0];       // [N, 64]
    const int*   ei  = (const int*)d_in[1];         // [2, E] int32 (JAX x64 off)
    const float* W_l = (const float*)d_in[2];       // [128, 64]
    const float* b_l = (const float*)d_in[3];       // [128]
    const float* W_r = (const float*)d_in[4];       // [128, 64]
    float*       out = (float*)d_out;               // [N, 128]

    int nN = in_sizes[0] / 64;
    int nE = in_sizes[1] / 2;

    int initN = (nN > 128 * 128) ? nN : 128 * 128;
    k_init<<<(initN + 255) / 256, 256>>>(W_l, W_r, nN);
    k_fill_buckets<<<(nE + 255) / 256, 256>>>(ei, nE, nN);
    k_aggregate<<<(nN + 7) / 8, 256>>>(x, nN);

    int smem_bytes = (64 * 128 + 64 * 128) * sizeof(float);   // 65536
    cudaFuncSetAttribute(k_gemm, cudaFuncAttributeMaxDynamicSharedMemorySize,
                         smem_bytes);
    k_gemm<<<(nN + 63) / 64, 256, smem_bytes>>>(x, b_l, out, nN);
}

// round 12
// speedup vs baseline: 1.6678x; 1.3477x over previous
#include <cuda_runtime.h>
#include <cuda_bf16.h>

// Problem constants (fixed-shape problem; grids still derived from in_sizes).
#define MAX_NODES 50000
#define CAP       128           // bucket capacity per node; P(deg>=128) ~ e^-150

// ---------------- device scratch (no allocations allowed) ----------------
__device__ int   g_deg[MAX_NODES];
__device__ int   g_bucket[MAX_NODES * CAP];     // 25.6 MB
__device__ float g_mean[MAX_NODES * 64];        // 12.8 MB
// Combined weight B[k][n] (k=in 0..127, n=out 0..127) pre-packed into
// mma.m16n8k16 B-fragment order: index [(kstep*16 + ntile)*32 + lane],
// uint2 = (b0, b1). Hi = bf16(v), Lo = bf16(v - hi).
__device__ __align__(16) uint2 g_WfH[8 * 16 * 32];   // 32 KB
__device__ __align__(16) uint2 g_WfL[8 * 16 * 32];   // 32 KB

// mma.sync m16n8k16 row.col f32.bf16.bf16.f32, D += A*B
#define MMA_BF16(d0, d1, d2, d3, a0, a1, a2, a3, b0, b1) \
    asm("mma.sync.aligned.m16n8k16.row.col.f32.bf16.bf16.f32 " \
        "{%0,%1,%2,%3}, {%4,%5,%6,%7}, {%8,%9}, {%0,%1,%2,%3};" \
        : "+f"(d0), "+f"(d1), "+f"(d2), "+f"(d3) \
        : "r"(a0), "r"(a1), "r"(a2), "r"(a3), "r"(b0), "r"(b1))

__device__ __forceinline__ float wval(const float* __restrict__ W_l,
                                      const float* __restrict__ W_r,
                                      int n, int k) {
    return (k < 64) ? W_l[n * 64 + k] : W_r[n * 64 + (k - 64)];
}

// split a float2 into packed bf16x2 hi and lo parts
__device__ __forceinline__ void split2(float2 v, unsigned int& h, unsigned int& l) {
    __nv_bfloat162 hp = __floats2bfloat162_rn(v.x, v.y);    // .x in low bits
    float h0 = __bfloat162float(hp.x);
    float h1 = __bfloat162float(hp.y);
    __nv_bfloat162 lp = __floats2bfloat162_rn(v.x - h0, v.y - h1);
    h = *(unsigned int*)&hp;
    l = *(unsigned int*)&lp;
}

// ---------------- kernel 1: zero degrees + build W fragment tables ----------
__global__ void k_init(const float* __restrict__ W_l,
                       const float* __restrict__ W_r, int nN) {
    int i = blockIdx.x * blockDim.x + threadIdx.x;
    if (i < nN) g_deg[i] = 0;
    if (i < 8 * 16 * 32) {
        int lane = i & 31;
        int nt   = (i >> 5) & 15;
        int ks   = i >> 9;
        int g    = lane >> 2;           // fragment "group" = n col within tile
        int t2   = (lane & 3) * 2;      // k row pair base
        int n    = nt * 8 + g;
        int k0   = ks * 16;
        // b0 = {B[k0+t2][n], B[k0+t2+1][n]}, b1 = rows +8
        float2 v0 = make_float2(wval(W_l, W_r, n, k0 + t2),
                                wval(W_l, W_r, n, k0 + t2 + 1));
        float2 v1 = make_float2(wval(W_l, W_r, n, k0 + t2 + 8),
                                wval(W_l, W_r, n, k0 + t2 + 9));
        unsigned int h0, l0, h1, l1;
        split2(v0, h0, l0);
        split2(v1, h1, l1);
        g_WfH[i] = make_uint2(h0, h1);
        g_WfL[i] = make_uint2(l0, l1);
    }
}

// ---------------- kernel 2: bucket fill (CSR-lite, no scan) ----------------
__global__ void k_fill_buckets(const int* __restrict__ ei, int nE, int nN) {
    int e = blockIdx.x * blockDim.x + threadIdx.x;
    if (e >= nE) return;
    int s = ei[e];               // src row   (edge_index[0][e])
    int d = ei[nE + e];          // dst row   (edge_index[1][e])
    if ((unsigned)s >= (unsigned)nN || (unsigned)d >= (unsigned)nN) return;
    int slot = atomicAdd(&g_deg[d], 1);
    if (slot < CAP) g_bucket[d * CAP + slot] = s;
}

// ---------------- kernel 3: mean aggregation (best measured version) ----------
__global__ void k_aggregate(const float* __restrict__ x, int nN) {
    int gwarp = (blockIdx.x * blockDim.x + threadIdx.x) >> 5;
    int lane  = threadIdx.x & 31;
    if (gwarp >= nN) return;
    int node = gwarp;
    int deg  = g_deg[node];
    int m    = min(deg, CAP);

    const float4* __restrict__ x4 = (const float4*)x;
    const int* __restrict__ bkt = &g_bucket[node * CAP];

    int col  = lane & 15;
    int half = lane >> 4;

    float4 acc = make_float4(0.f, 0.f, 0.f, 0.f);
    for (int base = 0; base < m; base += 32) {
        int cnt = min(32, m - base);
        int sid = (lane < cnt) ? bkt[base + lane] : -1;
        int pairs = (cnt + 1) >> 1;
        #pragma unroll 4
        for (int p = 0; p < pairs; p++) {
            int s = __shfl_sync(0xffffffffu, sid, 2 * p + half);
            if (s >= 0) {
                float4 v = x4[(size_t)s * 16 + col];
                acc.x += v.x; acc.y += v.y;
                acc.z += v.z; acc.w += v.w;
            }
        }
    }
    acc.x += __shfl_xor_sync(0xffffffffu, acc.x, 16);
    acc.y += __shfl_xor_sync(0xffffffffu, acc.y, 16);
    acc.z += __shfl_xor_sync(0xffffffffu, acc.z, 16);
    acc.w += __shfl_xor_sync(0xffffffffu, acc.w, 16);

    if (half == 0) {
        float inv = 1.0f / fmaxf((float)deg, 1.0f);
        acc.x *= inv; acc.y *= inv; acc.z *= inv; acc.w *= inv;
        ((float4*)g_mean)[(size_t)node * 16 + col] = acc;
    }
}

// ---------------- kernel 4: tensor-core GEMM via mma.sync (bf16 3-term split) --
// out[m, n] = sum_k A[m,k] * B[k,n] + bias[n],  A = [mean || x] (K=128)
// D = Ah*Bh + Ah*Bl + Al*Bh in fp32 accumulators (dropped Al*Bl <= 2^-18 rel).
// CTA: 128 nodes, 8 warps; warp w owns node rows [blockM + w*16, +16).
// Warp tiles: 16 n8-tiles x 8 k16-steps, 3 HMMA each = 384 HMMA/warp.
__global__ void __launch_bounds__(256, 2)
k_gemm_mma(const float* __restrict__ x,
           const float* __restrict__ b_l,
           float* __restrict__ out, int nN) {
    int tid  = threadIdx.x;
    int wid  = tid >> 5;
    int lane = tid & 31;
    int g    = lane >> 2;           // row within tile (and +8)
    int t2   = (lane & 3) * 2;      // col pair base (A cols / D cols)

    int row0 = blockIdx.x * 128 + wid * 16 + g;
    int row1 = row0 + 8;
    int nM   = nN - 1;
    size_t ro0 = (size_t)min(row0, nM) * 32;   // float2 row offsets (64 floats)
    size_t ro1 = (size_t)min(row1, nM) * 32;

    const float2* __restrict__ mean2 = (const float2*)g_mean;
    const float2* __restrict__ x2    = (const float2*)x;

    // accumulators: acc[nt][0..3]; c0,c1 = row g cols t2,t2+1; c2,c3 = row g+8
    float acc[16][4];
    #pragma unroll
    for (int nt = 0; nt < 16; nt++) {
        float b0 = b_l[nt * 8 + t2];
        float b1 = b_l[nt * 8 + t2 + 1];
        acc[nt][0] = b0; acc[nt][1] = b1;
        acc[nt][2] = b0; acc[nt][3] = b1;
    }

    #pragma unroll 1
    for (int ks = 0; ks < 8; ks++) {
        int k0 = ks * 16;
        const float2* __restrict__ src = (k0 < 64) ? mean2 : x2;
        int cb2 = ((k0 & 63) + t2) >> 1;       // float2 col index
        // A fragment: a0=(g, t2), a1=(g+8, t2), a2=(g, t2+8), a3=(g+8, t2+8)
        float2 v0 = src[ro0 + cb2];
        float2 v1 = src[ro1 + cb2];
        float2 v2 = src[ro0 + cb2 + 4];
        float2 v3 = src[ro1 + cb2 + 4];
        unsigned int ah0, ah1, ah2, ah3, al0, al1, al2, al3;
        split2(v0, ah0, al0);
        split2(v1, ah1, al1);
        split2(v2, ah2, al2);
        split2(v3, ah3, al3);

        const uint2* __restrict__ wh = &g_WfH[(ks * 16) * 32 + lane];
        const uint2* __restrict__ wl = &g_WfL[(ks * 16) * 32 + lane];
        #pragma unroll
        for (int nt = 0; nt < 16; nt++) {
            uint2 bh = wh[nt * 32];
            uint2 bl = wl[nt * 32];
            MMA_BF16(acc[nt][0], acc[nt][1], acc[nt][2], acc[nt][3],
                     ah0, ah1, ah2, ah3, bh.x, bh.y);
            MMA_BF16(acc[nt][0], acc[nt][1], acc[nt][2], acc[nt][3],
                     ah0, ah1, ah2, ah3, bl.x, bl.y);
            MMA_BF16(acc[nt][0], acc[nt][1], acc[nt][2], acc[nt][3],
                     al0, al1, al2, al3, bh.x, bh.y);
        }
    }

    // stores: float2 per (row, ntile); quad lanes cover 32B contiguous
    bool ok0 = row0 < nN;
    bool ok1 = row1 < nN;
    float* o0 = &out[(size_t)row0 * 128 + t2];
    float* o1 = &out[(size_t)row1 * 128 + t2];
    #pragma unroll
    for (int nt = 0; nt < 16; nt++) {
        if (ok0) *(float2*)(o0 + nt * 8) = make_float2(acc[nt][0], acc[nt][1]);
        if (ok1) *(float2*)(o1 + nt * 8) = make_float2(acc[nt][2], acc[nt][3]);
    }
}

// ---------------- launch ----------------
extern "C" void kernel_launch(void* const* d_in, const int* in_sizes, int n_in,
                              void* d_out, int out_size) {
    const float* x   = (const float*)d_in[0];       // [N, 64]
    const int*   ei  = (const int*)d_in[1];         // [2, E] int32 (JAX x64 off)
    const float* W_l = (const float*)d_in[2];       // [128, 64]
    const float* b_l = (const float*)d_in[3];       // [128]
    const float* W_r = (const float*)d_in[4];       // [128, 64]
    float*       out = (float*)d_out;               // [N, 128]

    int nN = in_sizes[0] / 64;
    int nE = in_sizes[1] / 2;

    int initN = (nN > 8 * 16 * 32) ? nN : 8 * 16 * 32;
    k_init<<<(initN + 255) / 256, 256>>>(W_l, W_r, nN);
    k_fill_buckets<<<(nE + 255) / 256, 256>>>(ei, nE, nN);
    k_aggregate<<<(nN + 7) / 8, 256>>>(x, nN);
    k_gemm_mma<<<(nN + 127) / 128, 256>>>(x, b_l, out, nN);
}